// round 15
// baseline (speedup 1.0000x reference)
#include <cuda_runtime.h>
#include <cuda_fp16.h>
#include <cstdint>

// ---------------- problem constants ----------------
#define GGRP   8
#define DDISP  64
#define EDIM   128
#define K1DIM  72            // G*9
#define MTOT   409600        // N*NS
#define TILE_M 256           // 8 warps x m32
#define NTILES 1600          // MTOT / TILE_M
#define GRID_X 152
#define NTHR   256           // 8 warps, each owns m32 x n128
#define EMB_ELEMS 52428800   // MTOT*EDIM
#define TOT_ELEMS 52838400   // + MTOT

// ---------------- smem layout (round-12 proven) ----------------
#define A1_STRIDE 44
#define BQ_S     264
#define NSTEP2   12                               // 8 real + 4 one-hot
#define REC_G    68
#define REC_WARP_BYTES (4*GGRP*REC_G*4)           // 8704

#define OFF_LABEL 0                               // 2 x 256 ints = 2048
#define OFF_BIAS1 2048
#define OFF_BIAS2 2560
#define OFF_B1    3072                            // 5*264*16 = 21120
#define OFF_B2    (OFF_B1 + 5*BQ_S*16)            // 12*264*16 = 50688
#define OFF_A1    (OFF_B2 + NSTEP2*BQ_S*16)       // 256*44*4 = 45056
#define OFF_REC   (OFF_A1 + TILE_M*A1_STRIDE*4)   // 8*8704 = 69632
#define SMEM_TOTAL (OFF_REC + 8*REC_WARP_BYTES)   // 189568 B

#define W2S_STRIDE 68                             // W2 staging in A1 region
#define WPT_STRIDE 66                             // WpT staging in REC region

// ---------------- helpers ----------------
__device__ __forceinline__ void mma_f16(float c[4], uint32_t a0, uint32_t a1,
                                        uint32_t a2, uint32_t a3,
                                        uint32_t b0, uint32_t b1) {
    asm volatile(
        "mma.sync.aligned.m16n8k16.row.col.f32.f16.f16.f32 "
        "{%0,%1,%2,%3}, {%4,%5,%6,%7}, {%8,%9}, {%0,%1,%2,%3};"
        : "+f"(c[0]), "+f"(c[1]), "+f"(c[2]), "+f"(c[3])
        : "r"(a0), "r"(a1), "r"(a2), "r"(a3), "r"(b0), "r"(b1));
}

__device__ __forceinline__ void ldsm_x4(uint32_t a[4], uint32_t addr) {
    asm volatile("ldmatrix.sync.aligned.m8n8.x4.shared.b16 {%0,%1,%2,%3}, [%4];"
        : "=r"(a[0]), "=r"(a[1]), "=r"(a[2]), "=r"(a[3]) : "r"(addr));
}

__device__ __forceinline__ float gelu_fast(float x) {
    float p = x * fmaf(x * x, 0.0713548163f, 1.5957691216f);
    float e;
    asm("ex2.approx.ftz.f32 %0, %1;" : "=f"(e) : "f"(-1.4426950408889634f * p));
    float r;
    asm("rcp.approx.ftz.f32 %0, %1;" : "=f"(r) : "f"(1.0f + e));
    return x * r;
}

__device__ __forceinline__ uint32_t pack_h2(float lo, float hi) {
    __half2 h = __floats2half2_rn(lo, hi);
    return *(uint32_t*)&h;
}

__device__ __forceinline__ uint32_t oh2(int d, int kb) {
    uint32_t r = (d == kb) ? 0x3C00u : 0u;
    if (d == kb + 1) r |= 0x3C000000u;
    return r;
}

__device__ __forceinline__ uint32_t smem_u32(const void* p) {
    uint32_t a;
    asm("{ .reg .u64 t; cvta.to.shared.u64 t, %1; cvt.u32.u64 %0, t; }" : "=r"(a) : "l"(p));
    return a;
}

#define CP_ASYNC16(dst, src) \
    asm volatile("cp.async.cg.shared.global [%0], [%1], 16;" :: "r"(dst), "l"(src))
#define CP_COMMIT()  asm volatile("cp.async.commit_group;")
#define CP_WAIT0()   asm volatile("cp.async.wait_group 0;")

// half index in B QUAD layout for element (k, n)
__device__ __forceinline__ int b_half_idx(int k, int n) {
    int kp = k >> 1, h = k & 1;
    int s = kp >> 3, rem = kp & 7;
    int ti = rem & 3, w = rem >> 2;
    int g = n & 7, j = n >> 3, jp = j >> 1, jh = j & 1;
    int word = s * (BQ_S * 4) + ti * 264 + jp * 32 + g * 4 + jh * 2 + w;
    return word * 2 + h;
}

// ---- branchless 12->9 window select (validated) ----
struct GWin { int qb; bool o1, o2, neg, a1, a2, a4; };
__device__ __forceinline__ GWin gwin(int dcl) {
    int base = dcl - 4;
    int st = base < 0 ? 0 : (base > 55 ? 55 : base);
    int lo = base - st;
    GWin w;
    w.qb = st >> 2;
    int off = st & 3;
    w.o1 = off & 1;  w.o2 = off & 2;
    w.neg = lo < 0;
    int a = w.neg ? -lo : lo;
    w.a1 = a & 1;  w.a2 = a & 2;  w.a4 = a & 4;
    return w;
}

__device__ __forceinline__ void gselect(const GWin& w, const float4 c[3], float v[9]) {
    float f[12] = {c[0].x, c[0].y, c[0].z, c[0].w,
                   c[1].x, c[1].y, c[1].z, c[1].w,
                   c[2].x, c[2].y, c[2].z, c[2].w};
    float t[11], h[9];
    #pragma unroll
    for (int i = 0; i < 11; i++) t[i] = w.o1 ? f[i + 1] : f[i];
    #pragma unroll
    for (int i = 0; i < 9; i++)  h[i] = w.o2 ? t[i + 2] : t[i];
    #pragma unroll
    for (int i = 0; i < 9; i++) {
        float sh = w.neg ? h[i > 0 ? i - 1 : 0] : h[i < 8 ? i + 1 : 8];
        t[i] = w.a1 ? sh : h[i];
    }
    #pragma unroll
    for (int i = 0; i < 9; i++) {
        float sh = w.neg ? t[i > 1 ? i - 2 : 0] : t[i < 7 ? i + 2 : 8];
        h[i] = w.a2 ? sh : t[i];
    }
    #pragma unroll
    for (int i = 0; i < 9; i++) {
        float sh = w.neg ? h[i > 3 ? i - 4 : 0] : h[i < 5 ? i + 4 : 8];
        v[i] = w.a4 ? sh : h[i];
    }
}

// stage 4 pixel records (8 KB) densely via cp.async
__device__ __forceinline__ void stage_records(uint32_t rec_sa, const float* __restrict__ gsrc,
                                              int lid) {
    #pragma unroll
    for (int u = 0; u < 16; u++) {
        int p = u >> 2, gg = (u & 3) * 2 + (lid >> 4);
        uint32_t dst = rec_sa + (((p * GGRP + gg) * REC_G + (lid & 15) * 4)) * 4;
        CP_ASYNC16(dst, gsrc + u * 128);
    }
    CP_COMMIT();
}

// extract this thread's 4 group-windows -> 18 packed words
__device__ __forceinline__ void extract_windows(const float* __restrict__ recw, int prow,
                                                int grp4, const GWin& w, uint32_t* Gdst) {
    #pragma unroll
    for (int e = 0; e < 2; e++) {
        float4 ck[2][3];
        #pragma unroll
        for (int gi = 0; gi < 2; gi++) {
            const float4* s4 = (const float4*)(recw + (prow * GGRP + grp4 + 2 * e + gi) * REC_G)
                               + w.qb;
            ck[gi][0] = s4[0];  ck[gi][1] = s4[1];  ck[gi][2] = s4[2];
        }
        float v[9];
        gselect(w, ck[0], v);
        #pragma unroll
        for (int q = 0; q < 4; q++) Gdst[9 * e + q] = pack_h2(v[2 * q], v[2 * q + 1]);
        float v8 = v[8];
        gselect(w, ck[1], v);
        Gdst[9 * e + 4] = pack_h2(v8, v[0]);
        #pragma unroll
        for (int q = 0; q < 4; q++) Gdst[9 * e + 5 + q] = pack_h2(v[2 * q + 1], v[2 * q + 2]);
    }
}

// ---------------- single fused kernel ----------------
__global__ void __launch_bounds__(NTHR, 1)
propagation_kernel(const float* __restrict__ cost, const int* __restrict__ label,
                   const float* __restrict__ W1, const float* __restrict__ b1,
                   const float* __restrict__ W2, const float* __restrict__ b2,
                   const float* __restrict__ Wp,
                   float* __restrict__ out_embed, float* __restrict__ out_label) {
    extern __shared__ char smem[];
    const int tid = threadIdx.x;
    const int wid = tid >> 5, lid = tid & 31;
    const int g = lid >> 2, ti = lid & 3;
    const int mbase = wid * 32;
    const int fb = wid * 16;
    const int erow = lid >> 1;
    const int grp4 = (lid & 1) * 4;
    const int prow = lid >> 3;

    int*      labels_s = (int*)(smem + OFF_LABEL);
    float*    b1s   = (float*)(smem + OFF_BIAS1);
    float*    b2ps  = (float*)(smem + OFF_BIAS2);
    const uint4* B1q = (const uint4*)(smem + OFF_B1);
    const uint4* B2q = (const uint4*)(smem + OFF_B2);
    __half*   B1h   = (__half*)(smem + OFF_B1);
    __half*   B2h   = (__half*)(smem + OFF_B2);
    uint32_t* A1u   = (uint32_t*)(smem + OFF_A1);
    float*    recw  = (float*)(smem + OFF_REC + wid * REC_WARP_BYTES);
    const uint32_t rec_sa = smem_u32(recw);

    // ================= PROLOGUE (identical to round 12) =================
    {
        __half* W2sh  = (__half*)(smem + OFF_A1);
        __half* WpTsh = (__half*)(smem + OFF_REC);
        for (int idx = tid; idx < EDIM * EDIM; idx += NTHR) {
            int r = idx >> 7, j = idx & 127;
            W2sh[(r * W2S_STRIDE + (j >> 1)) * 2 + (j & 1)] = __float2half(__ldg(W2 + idx));
            int jj = idx >> 7, n = idx & 127;
            WpTsh[(n * WPT_STRIDE + (jj >> 1)) * 2 + (jj & 1)] = __float2half(__ldg(Wp + idx));
        }
        for (int idx = tid; idx < K1DIM * EDIM; idx += NTHR) {
            int k = idx >> 7, n = idx & 127;
            B1h[b_half_idx(k, n)] = __float2half(__ldg(W1 + idx));
        }
        for (int i = tid; i < 512; i += NTHR) {
            int t4 = i >> 7, rem = i & 127;
            int jp = rem >> 4, gg = (rem >> 1) & 7, jh = rem & 1;
            ((uint32_t*)(smem + OFF_B1))[4 * (BQ_S * 4) + t4 * 264 + jp * 32 + gg * 4 + jh * 2 + 1] = 0;
        }
        if (tid < EDIM) b1s[tid] = __ldg(b1 + tid);
    }
    __syncthreads();

    {   // fold W2p = W2 @ Wp_top via tensor cores -> B2 steps 0..7
        const uint32_t* W2s  = (const uint32_t*)(smem + OFF_A1);
        const uint32_t* WpTs = (const uint32_t*)(smem + OFF_REC);
        float facc[16][4];
        #pragma unroll
        for (int j = 0; j < 16; j++)
            #pragma unroll
            for (int u = 0; u < 4; u++) facc[j][u] = 0.f;
        #pragma unroll
        for (int s = 0; s < 8; s++) {
            int jp0 = 8 * s + ti;
            uint32_t a0 = W2s[(fb + g) * W2S_STRIDE + jp0];
            uint32_t a1 = W2s[(fb + g + 8) * W2S_STRIDE + jp0];
            uint32_t a2 = W2s[(fb + g) * W2S_STRIDE + jp0 + 4];
            uint32_t a3 = W2s[(fb + g + 8) * W2S_STRIDE + jp0 + 4];
            #pragma unroll
            for (int j = 0; j < 16; j++) {
                uint32_t b0 = WpTs[(8 * j + g) * WPT_STRIDE + jp0];
                uint32_t b1v = WpTs[(8 * j + g) * WPT_STRIDE + jp0 + 4];
                mma_f16(facc[j], a0, a1, a2, a3, b0, b1v);
            }
        }
        #pragma unroll
        for (int j = 0; j < 16; j++) {
            int n0 = 8 * j + 2 * ti;
            B2h[b_half_idx(fb + g, n0)]     = __float2half(facc[j][0]);
            B2h[b_half_idx(fb + g, n0 + 1)] = __float2half(facc[j][1]);
            B2h[b_half_idx(fb + g + 8, n0)]     = __float2half(facc[j][2]);
            B2h[b_half_idx(fb + g + 8, n0 + 1)] = __float2half(facc[j][3]);
        }
        if (tid < EDIM) {
            float ba = 0.f;
            #pragma unroll 8
            for (int j = 0; j < EDIM; j++) ba += __ldg(b2 + j) * __ldg(Wp + (size_t)j * EDIM + tid);
            b2ps[tid] = ba;
        }
    }
    __syncthreads();

    {   // fourier scratch in A1 region
        float* scr = (float*)(smem + OFF_A1);
        for (int t = tid; t < 960; t += NTHR) {
            int d = t / 15, i = t - d * 15;
            float coordf = (float)d * (float)(3.14 / 64.0);
            float fr = coordf * (float)(1 << i);
            scr[d * 32 + i]      = (float)sin((double)fr);
            scr[d * 32 + 15 + i] = (float)cos((double)fr);
            if (i == 0) scr[d * 32 + 30] = coordf;
        }
    }
    __syncthreads();

    {   // table rows -> B2 steps 8..11
        const float* scr = (const float*)(smem + OFF_A1);
        int n = tid & 127, dh = tid >> 7;
        float wpc[31];
        #pragma unroll
        for (int c = 0; c < 31; c++) wpc[c] = __ldg(Wp + (size_t)(EDIM + c) * EDIM + n);
        float bb = b2ps[n];
        #pragma unroll 4
        for (int u = 0; u < 32; u++) {
            int d = dh + 2 * u;
            float acc = bb;
            #pragma unroll
            for (int c = 0; c < 31; c++) acc += scr[d * 32 + c] * wpc[c];
            B2h[b_half_idx(128 + d, n)] = __float2half(acc);
        }
    }
    __syncthreads();

    // zero A1 K-pad words (kp 36..39) for this warp's 32 rows
    uint32_t* A1w = A1u + mbase * A1_STRIDE;
    for (int i = lid; i < 128; i += 32)
        A1w[(i >> 2) * A1_STRIDE + 36 + (i & 3)] = 0;

    uint32_t* GdstA = A1w + erow * A1_STRIDE + (lid & 1) * 18;
    uint32_t* GdstB = A1w + (16 + erow) * A1_STRIDE + (lid & 1) * 18;

    const uint32_t a1_sa = smem_u32(A1w);
    const uint32_t a_base0 = a1_sa + (((lid & 15) * A1_STRIDE + (lid >> 4) * 4) << 2);
    const uint32_t a_base1 = a_base0 + 16 * A1_STRIDE * 4;

    // first tile: stage + extract both batches
    {
        int t0 = blockIdx.x;
        #pragma unroll
        for (int b = 0; b < 2; b++) {
            int pix0 = t0 * (TILE_M / 4) + wid * 8 + b * 4;
            stage_records(rec_sa, cost + (size_t)pix0 * (GGRP * DDISP) + lid * 4, lid);
            int row = 16 * b + erow;
            int draw = __ldg(label + t0 * TILE_M + mbase + row);
            if ((lid & 1) == 0) {
                labels_s[mbase + row] = draw;
                if (out_label) out_label[t0 * TILE_M + mbase + row] = (float)draw;
            }
            CP_WAIT0();
            __syncwarp();
            int dcl = draw < 0 ? 0 : (draw > 63 ? 63 : draw);
            GWin w = gwin(dcl);
            extract_windows(recw, prow, grp4, w, b ? GdstB : GdstA);
            __syncwarp();
        }
    }

    // ================= MAIN LOOP =================
    int cb = 0;
    for (int tile = blockIdx.x; tile < NTILES; tile += GRID_X) {
        const int m0 = tile * TILE_M;
        const int nxt = tile + GRID_X;
        const bool hn = nxt < NTILES;

        int drawA = 0, drawB = 0;
        if (hn) {
            drawA = __ldg(label + nxt * TILE_M + mbase + erow);
            drawB = __ldg(label + nxt * TILE_M + mbase + 16 + erow);
        }

        int dga[2], dgb[2];
        #pragma unroll
        for (int i = 0; i < 2; i++) {
            int d0 = labels_s[cb * TILE_M + mbase + 16 * i + g];
            int d1 = labels_s[cb * TILE_M + mbase + 16 * i + g + 8];
            dga[i] = d0 < 0 ? 0 : (d0 > 63 ? 63 : d0);
            dgb[i] = d1 < 0 ? 0 : (d1 > 63 ? 63 : d1);
        }

        // ---- GEMM1 (two n-halves): batch-loaded B quads -> ha[2][8][4] ----
        uint32_t ha[2][8][4];
        #pragma unroll
        for (int hf = 0; hf < 2; hf++) {
            float acc1[2][8][4];
            #pragma unroll
            for (int i = 0; i < 2; i++)
                #pragma unroll
                for (int j = 0; j < 8; j++)
                    #pragma unroll
                    for (int u = 0; u < 4; u++) acc1[i][j][u] = 0.f;
            #pragma unroll
            for (int s = 0; s < 5; s++) {
                uint32_t a[2][4];
                ldsm_x4(a[0], a_base0 + s * 32);
                ldsm_x4(a[1], a_base1 + s * 32);
                const uint4* bq = B1q + s * BQ_S + ti * 66 + (4 * hf) * 8 + g;
                uint4 bb[4];
                #pragma unroll
                for (int jp = 0; jp < 4; jp++) bb[jp] = bq[jp * 8];
                #pragma unroll
                for (int jp = 0; jp < 4; jp++) {
                    mma_f16(acc1[0][2 * jp],     a[0][0], a[0][1], a[0][2], a[0][3], bb[jp].x, bb[jp].y);
                    mma_f16(acc1[1][2 * jp],     a[1][0], a[1][1], a[1][2], a[1][3], bb[jp].x, bb[jp].y);
                    mma_f16(acc1[0][2 * jp + 1], a[0][0], a[0][1], a[0][2], a[0][3], bb[jp].z, bb[jp].w);
                    mma_f16(acc1[1][2 * jp + 1], a[1][0], a[1][1], a[1][2], a[1][3], bb[jp].z, bb[jp].w);
                }
            }
            #pragma unroll
            for (int sl = 0; sl < 4; sl++) {
                int j0 = 2 * sl, j1 = 2 * sl + 1;
                float2 bb0 = *(const float2*)(b1s + 64 * hf + 8 * j0 + 2 * ti);
                float2 bb1 = *(const float2*)(b1s + 64 * hf + 8 * j1 + 2 * ti);
                #pragma unroll
                for (int i = 0; i < 2; i++) {
                    ha[i][4 * hf + sl][0] = pack_h2(gelu_fast(acc1[i][j0][0] + bb0.x),
                                                   gelu_fast(acc1[i][j0][1] + bb0.y));
                    ha[i][4 * hf + sl][1] = pack_h2(gelu_fast(acc1[i][j0][2] + bb0.x),
                                                   gelu_fast(acc1[i][j0][3] + bb0.y));
                    ha[i][4 * hf + sl][2] = pack_h2(gelu_fast(acc1[i][j1][0] + bb1.x),
                                                   gelu_fast(acc1[i][j1][1] + bb1.y));
                    ha[i][4 * hf + sl][3] = pack_h2(gelu_fast(acc1[i][j1][2] + bb1.x),
                                                   gelu_fast(acc1[i][j1][3] + bb1.y));
                }
            }
        }
        __syncwarp();   // A1 fully consumed

        // ---- stage batch A of next tile ----
        if (hn) {
            int pix0 = nxt * (TILE_M / 4) + wid * 8;
            stage_records(rec_sa, cost + (size_t)pix0 * (GGRP * DDISP) + lid * 4, lid);
        }

        // ---- GEMM2 + epilogue in 4 n-quarters with B prefetch ----
        #pragma unroll
        for (int q = 0; q < 4; q++) {
            float acc2[2][4][4];
            #pragma unroll
            for (int i = 0; i < 2; i++)
                #pragma unroll
                for (int j = 0; j < 4; j++)
                    #pragma unroll
                    for (int u = 0; u < 4; u++) acc2[i][j][u] = 0.f;

            const uint4* bqbase = B2q + ti * 66 + (2 * q) * 8 + g;
            // prefetch s=0
            uint4 bc0 = bqbase[0], bc1 = bqbase[8];
            #pragma unroll
            for (int s = 0; s < 12; s++) {
                // prefetch s+1 before using s
                uint4 bn0, bn1;
                if (s < 11) {
                    bn0 = bqbase[(s + 1) * BQ_S];
                    bn1 = bqbase[(s + 1) * BQ_S + 8];
                }
                if (s < 8) {
                    mma_f16(acc2[0][0], ha[0][s][0], ha[0][s][1], ha[0][s][2], ha[0][s][3], bc0.x, bc0.y);
                    mma_f16(acc2[1][0], ha[1][s][0], ha[1][s][1], ha[1][s][2], ha[1][s][3], bc0.x, bc0.y);
                    mma_f16(acc2[0][1], ha[0][s][0], ha[0][s][1], ha[0][s][2], ha[0][s][3], bc0.z, bc0.w);
                    mma_f16(acc2[1][1], ha[1][s][0], ha[1][s][1], ha[1][s][2], ha[1][s][3], bc0.z, bc0.w);
                    mma_f16(acc2[0][2], ha[0][s][0], ha[0][s][1], ha[0][s][2], ha[0][s][3], bc1.x, bc1.y);
                    mma_f16(acc2[1][2], ha[1][s][0], ha[1][s][1], ha[1][s][2], ha[1][s][3], bc1.x, bc1.y);
                    mma_f16(acc2[0][3], ha[0][s][0], ha[0][s][1], ha[0][s][2], ha[0][s][3], bc1.z, bc1.w);
                    mma_f16(acc2[1][3], ha[1][s][0], ha[1][s][1], ha[1][s][2], ha[1][s][3], bc1.z, bc1.w);
                } else {
                    int so = s - 8;
                    int kb = 16 * so + 2 * ti;
                    #pragma unroll
                    for (int i = 0; i < 2; i++) {
                        uint32_t a0 = oh2(dga[i], kb);
                        uint32_t a1 = oh2(dgb[i], kb);
                        uint32_t a2 = oh2(dga[i], kb + 8);
                        uint32_t a3 = oh2(dgb[i], kb + 8);
                        mma_f16(acc2[i][0], a0, a1, a2, a3, bc0.x, bc0.y);
                        mma_f16(acc2[i][1], a0, a1, a2, a3, bc0.z, bc0.w);
                        mma_f16(acc2[i][2], a0, a1, a2, a3, bc1.x, bc1.y);
                        mma_f16(acc2[i][3], a0, a1, a2, a3, bc1.z, bc1.w);
                    }
                }
                bc0 = bn0;  bc1 = bn1;
            }
            // epilogue for this quarter
            #pragma unroll
            for (int i = 0; i < 2; i++) {
                float* o0 = out_embed + (size_t)(m0 + mbase + 16 * i + g) * EDIM + 32 * q + 2 * ti;
                float* o1 = out_embed + (size_t)(m0 + mbase + 16 * i + g + 8) * EDIM + 32 * q + 2 * ti;
                #pragma unroll
                for (int j = 0; j < 4; j++) {
                    *(float2*)(o0 + 8 * j) = make_float2(acc2[i][j][0], acc2[i][j][1]);
                    *(float2*)(o1 + 8 * j) = make_float2(acc2[i][j][2], acc2[i][j][3]);
                }
            }

            // after quarter 1: land batch A, extract, stage batch B
            if (q == 1 && hn) {
                CP_WAIT0();
                __syncwarp();
                int dcl = drawA < 0 ? 0 : (drawA > 63 ? 63 : drawA);
                GWin w = gwin(dcl);
                extract_windows(recw, prow, grp4, w, GdstA);
                if ((lid & 1) == 0) {
                    labels_s[(cb ^ 1) * TILE_M + mbase + erow] = drawA;
                    if (out_label) out_label[nxt * TILE_M + mbase + erow] = (float)drawA;
                }
                __syncwarp();
                int pix0 = nxt * (TILE_M / 4) + wid * 8 + 4;
                stage_records(rec_sa, cost + (size_t)pix0 * (GGRP * DDISP) + lid * 4, lid);
            }
        }

        // ---- land batch B, extract ----
        if (hn) {
            CP_WAIT0();
            __syncwarp();
            int dcl = drawB < 0 ? 0 : (drawB > 63 ? 63 : drawB);
            GWin w = gwin(dcl);
            extract_windows(recw, prow, grp4, w, GdstB);
            if ((lid & 1) == 0) {
                labels_s[(cb ^ 1) * TILE_M + mbase + 16 + erow] = drawB;
                if (out_label) out_label[nxt * TILE_M + mbase + 16 + erow] = (float)drawB;
            }
        }
        __syncwarp();
        cb ^= 1;
    }
}

// ---------------- launch ----------------
extern "C" void kernel_launch(void* const* d_in, const int* in_sizes, int n_in,
                              void* d_out, int out_size) {
    const float* cost  = (const float*)d_in[0];
    const int*   label = (const int*)d_in[1];
    // d_in[2] = context (unused: layers=[] passthrough)
    const float* W1 = (const float*)d_in[3];
    const float* b1 = (const float*)d_in[4];
    const float* W2 = (const float*)d_in[5];
    const float* b2 = (const float*)d_in[6];
    const float* Wp = (const float*)d_in[7];

    float* out = (float*)d_out;
    float* out_label = (out_size >= TOT_ELEMS) ? (out + EMB_ELEMS) : nullptr;

    cudaFuncSetAttribute(propagation_kernel,
                         cudaFuncAttributeMaxDynamicSharedMemorySize, SMEM_TOTAL);

    propagation_kernel<<<GRID_X, NTHR, SMEM_TOTAL>>>(cost, label, W1, b1, W2, b2, Wp,
                                                     out, out_label);
}

// round 16
// speedup vs baseline: 1.4927x; 1.4927x over previous
#include <cuda_runtime.h>
#include <cuda_fp16.h>
#include <cstdint>

// ---------------- problem constants ----------------
#define GGRP   8
#define DDISP  64
#define EDIM   128
#define K1DIM  72            // G*9
#define MTOT   409600        // N*NS
#define TILE_M 256           // 8 warps x m32
#define NTILES 1600          // MTOT / TILE_M
#define GRID_X 152
#define NTHR   256           // 8 warps, each owns m32 x n128
#define EMB_ELEMS 52428800   // MTOT*EDIM
#define TOT_ELEMS 52838400   // + MTOT

// ---------------- smem layout (round-12 proven) ----------------
#define A1_STRIDE 44
#define BQ_S     264
#define NSTEP2   12                               // 8 real + 4 one-hot
#define REC_G    68
#define REC_WARP_BYTES (4*GGRP*REC_G*4)           // 8704

#define OFF_LABEL 0                               // 2 x 256 ints = 2048
#define OFF_BIAS1 2048
#define OFF_BIAS2 2560
#define OFF_B1    3072                            // 5*264*16 = 21120
#define OFF_B2    (OFF_B1 + 5*BQ_S*16)            // 12*264*16 = 50688
#define OFF_A1    (OFF_B2 + NSTEP2*BQ_S*16)       // 256*44*4 = 45056
#define OFF_REC   (OFF_A1 + TILE_M*A1_STRIDE*4)   // 8*8704 = 69632
#define SMEM_TOTAL (OFF_REC + 8*REC_WARP_BYTES)   // 189568 B

#define W2S_STRIDE 68                             // W2 staging in A1 region
#define WPT_STRIDE 66                             // WpT staging in REC region

// ---------------- helpers ----------------
__device__ __forceinline__ void mma_f16(float c[4], uint32_t a0, uint32_t a1,
                                        uint32_t a2, uint32_t a3,
                                        uint32_t b0, uint32_t b1) {
    asm volatile(
        "mma.sync.aligned.m16n8k16.row.col.f32.f16.f16.f32 "
        "{%0,%1,%2,%3}, {%4,%5,%6,%7}, {%8,%9}, {%0,%1,%2,%3};"
        : "+f"(c[0]), "+f"(c[1]), "+f"(c[2]), "+f"(c[3])
        : "r"(a0), "r"(a1), "r"(a2), "r"(a3), "r"(b0), "r"(b1));
}

__device__ __forceinline__ void ldsm_x4(uint32_t a[4], uint32_t addr) {
    asm volatile("ldmatrix.sync.aligned.m8n8.x4.shared.b16 {%0,%1,%2,%3}, [%4];"
        : "=r"(a[0]), "=r"(a[1]), "=r"(a[2]), "=r"(a[3]) : "r"(addr));
}

__device__ __forceinline__ float gelu_fast(float x) {
    float p = x * fmaf(x * x, 0.0713548163f, 1.5957691216f);
    float e;
    asm("ex2.approx.ftz.f32 %0, %1;" : "=f"(e) : "f"(-1.4426950408889634f * p));
    float r;
    asm("rcp.approx.ftz.f32 %0, %1;" : "=f"(r) : "f"(1.0f + e));
    return x * r;
}

__device__ __forceinline__ uint32_t pack_h2(float lo, float hi) {
    __half2 h = __floats2half2_rn(lo, hi);
    return *(uint32_t*)&h;
}

__device__ __forceinline__ uint32_t oh2(int d, int kb) {
    uint32_t r = (d == kb) ? 0x3C00u : 0u;
    if (d == kb + 1) r |= 0x3C000000u;
    return r;
}

__device__ __forceinline__ uint32_t smem_u32(const void* p) {
    uint32_t a;
    asm("{ .reg .u64 t; cvta.to.shared.u64 t, %1; cvt.u32.u64 %0, t; }" : "=r"(a) : "l"(p));
    return a;
}

#define CP_ASYNC16(dst, src) \
    asm volatile("cp.async.cg.shared.global [%0], [%1], 16;" :: "r"(dst), "l"(src))
#define CP_COMMIT()  asm volatile("cp.async.commit_group;")
#define CP_WAIT0()   asm volatile("cp.async.wait_group 0;")

// half index in B QUAD layout for element (k, n)
__device__ __forceinline__ int b_half_idx(int k, int n) {
    int kp = k >> 1, h = k & 1;
    int s = kp >> 3, rem = kp & 7;
    int ti = rem & 3, w = rem >> 2;
    int g = n & 7, j = n >> 3, jp = j >> 1, jh = j & 1;
    int word = s * (BQ_S * 4) + ti * 264 + jp * 32 + g * 4 + jh * 2 + w;
    return word * 2 + h;
}

// ---- branchless 12->9 window select (validated) ----
struct GWin { int qb; bool o1, o2, neg, a1, a2, a4; };
__device__ __forceinline__ GWin gwin(int dcl) {
    int base = dcl - 4;
    int st = base < 0 ? 0 : (base > 55 ? 55 : base);
    int lo = base - st;
    GWin w;
    w.qb = st >> 2;
    int off = st & 3;
    w.o1 = off & 1;  w.o2 = off & 2;
    w.neg = lo < 0;
    int a = w.neg ? -lo : lo;
    w.a1 = a & 1;  w.a2 = a & 2;  w.a4 = a & 4;
    return w;
}

__device__ __forceinline__ void gselect(const GWin& w, const float4 c[3], float v[9]) {
    float f[12] = {c[0].x, c[0].y, c[0].z, c[0].w,
                   c[1].x, c[1].y, c[1].z, c[1].w,
                   c[2].x, c[2].y, c[2].z, c[2].w};
    float t[11], h[9];
    #pragma unroll
    for (int i = 0; i < 11; i++) t[i] = w.o1 ? f[i + 1] : f[i];
    #pragma unroll
    for (int i = 0; i < 9; i++)  h[i] = w.o2 ? t[i + 2] : t[i];
    #pragma unroll
    for (int i = 0; i < 9; i++) {
        float sh = w.neg ? h[i > 0 ? i - 1 : 0] : h[i < 8 ? i + 1 : 8];
        t[i] = w.a1 ? sh : h[i];
    }
    #pragma unroll
    for (int i = 0; i < 9; i++) {
        float sh = w.neg ? t[i > 1 ? i - 2 : 0] : t[i < 7 ? i + 2 : 8];
        h[i] = w.a2 ? sh : t[i];
    }
    #pragma unroll
    for (int i = 0; i < 9; i++) {
        float sh = w.neg ? h[i > 3 ? i - 4 : 0] : h[i < 5 ? i + 4 : 8];
        v[i] = w.a4 ? sh : h[i];
    }
}

// stage 4 pixel records (8 KB) densely via cp.async
__device__ __forceinline__ void stage_records(uint32_t rec_sa, const float* __restrict__ gsrc,
                                              int lid) {
    #pragma unroll
    for (int u = 0; u < 16; u++) {
        int p = u >> 2, gg = (u & 3) * 2 + (lid >> 4);
        uint32_t dst = rec_sa + (((p * GGRP + gg) * REC_G + (lid & 15) * 4)) * 4;
        CP_ASYNC16(dst, gsrc + u * 128);
    }
    CP_COMMIT();
}

// extract this thread's 4 group-windows -> 18 packed words
__device__ __forceinline__ void extract_windows(const float* __restrict__ recw, int prow,
                                                int grp4, const GWin& w, uint32_t* Gdst) {
    #pragma unroll
    for (int e = 0; e < 2; e++) {
        float4 ck[2][3];
        #pragma unroll
        for (int gi = 0; gi < 2; gi++) {
            const float4* s4 = (const float4*)(recw + (prow * GGRP + grp4 + 2 * e + gi) * REC_G)
                               + w.qb;
            ck[gi][0] = s4[0];  ck[gi][1] = s4[1];  ck[gi][2] = s4[2];
        }
        float v[9];
        gselect(w, ck[0], v);
        #pragma unroll
        for (int q = 0; q < 4; q++) Gdst[9 * e + q] = pack_h2(v[2 * q], v[2 * q + 1]);
        float v8 = v[8];
        gselect(w, ck[1], v);
        Gdst[9 * e + 4] = pack_h2(v8, v[0]);
        #pragma unroll
        for (int q = 0; q < 4; q++) Gdst[9 * e + 5 + q] = pack_h2(v[2 * q + 1], v[2 * q + 2]);
    }
}

// ---------------- single fused kernel ----------------
__global__ void __launch_bounds__(NTHR, 1)
propagation_kernel(const float* __restrict__ cost, const int* __restrict__ label,
                   const float* __restrict__ W1, const float* __restrict__ b1,
                   const float* __restrict__ W2, const float* __restrict__ b2,
                   const float* __restrict__ Wp,
                   float* __restrict__ out_embed, float* __restrict__ out_label) {
    extern __shared__ char smem[];
    const int tid = threadIdx.x;
    const int wid = tid >> 5, lid = tid & 31;
    const int g = lid >> 2, ti = lid & 3;
    const int mbase = wid * 32;               // warp owns rows [mbase, mbase+32)
    const int fb = wid * 16;                  // prologue fold row base
    const int erow = lid >> 1;                // extract row within 16-row batch
    const int grp4 = (lid & 1) * 4;
    const int prow = lid >> 3;                // local pixel 0..3 in a batch

    int*      labels_s = (int*)(smem + OFF_LABEL);
    float*    b1s   = (float*)(smem + OFF_BIAS1);
    float*    b2ps  = (float*)(smem + OFF_BIAS2);
    const uint4* B1q = (const uint4*)(smem + OFF_B1);
    const uint4* B2q = (const uint4*)(smem + OFF_B2);
    __half*   B1h   = (__half*)(smem + OFF_B1);
    __half*   B2h   = (__half*)(smem + OFF_B2);
    uint32_t* A1u   = (uint32_t*)(smem + OFF_A1);
    float*    recw  = (float*)(smem + OFF_REC + wid * REC_WARP_BYTES);
    const uint32_t rec_sa = smem_u32(recw);

    // ================= PROLOGUE =================
    {
        __half* W2sh  = (__half*)(smem + OFF_A1);
        __half* WpTsh = (__half*)(smem + OFF_REC);
        for (int idx = tid; idx < EDIM * EDIM; idx += NTHR) {
            int r = idx >> 7, j = idx & 127;
            W2sh[(r * W2S_STRIDE + (j >> 1)) * 2 + (j & 1)] = __float2half(__ldg(W2 + idx));
            int jj = idx >> 7, n = idx & 127;
            WpTsh[(n * WPT_STRIDE + (jj >> 1)) * 2 + (jj & 1)] = __float2half(__ldg(Wp + idx));
        }
        for (int idx = tid; idx < K1DIM * EDIM; idx += NTHR) {
            int k = idx >> 7, n = idx & 127;
            B1h[b_half_idx(k, n)] = __float2half(__ldg(W1 + idx));
        }
        // zero B1 pad words (kp 36..39 -> s=4, w=1)
        for (int i = tid; i < 512; i += NTHR) {
            int t4 = i >> 7, rem = i & 127;
            int jp = rem >> 4, gg = (rem >> 1) & 7, jh = rem & 1;
            ((uint32_t*)(smem + OFF_B1))[4 * (BQ_S * 4) + t4 * 264 + jp * 32 + gg * 4 + jh * 2 + 1] = 0;
        }
        if (tid < EDIM) b1s[tid] = __ldg(b1 + tid);
    }
    __syncthreads();

    {   // fold W2p = W2 @ Wp_top via tensor cores -> B2 steps 0..7 (fold rows fb..fb+15)
        const uint32_t* W2s  = (const uint32_t*)(smem + OFF_A1);
        const uint32_t* WpTs = (const uint32_t*)(smem + OFF_REC);
        float facc[16][4];
        #pragma unroll
        for (int j = 0; j < 16; j++)
            #pragma unroll
            for (int u = 0; u < 4; u++) facc[j][u] = 0.f;
        #pragma unroll
        for (int s = 0; s < 8; s++) {
            int jp0 = 8 * s + ti;
            uint32_t a0 = W2s[(fb + g) * W2S_STRIDE + jp0];
            uint32_t a1 = W2s[(fb + g + 8) * W2S_STRIDE + jp0];
            uint32_t a2 = W2s[(fb + g) * W2S_STRIDE + jp0 + 4];
            uint32_t a3 = W2s[(fb + g + 8) * W2S_STRIDE + jp0 + 4];
            #pragma unroll
            for (int j = 0; j < 16; j++) {
                uint32_t b0 = WpTs[(8 * j + g) * WPT_STRIDE + jp0];
                uint32_t b1v = WpTs[(8 * j + g) * WPT_STRIDE + jp0 + 4];
                mma_f16(facc[j], a0, a1, a2, a3, b0, b1v);
            }
        }
        #pragma unroll
        for (int j = 0; j < 16; j++) {
            int n0 = 8 * j + 2 * ti;
            B2h[b_half_idx(fb + g, n0)]     = __float2half(facc[j][0]);
            B2h[b_half_idx(fb + g, n0 + 1)] = __float2half(facc[j][1]);
            B2h[b_half_idx(fb + g + 8, n0)]     = __float2half(facc[j][2]);
            B2h[b_half_idx(fb + g + 8, n0 + 1)] = __float2half(facc[j][3]);
        }
        if (tid < EDIM) {
            float ba = 0.f;
            #pragma unroll 8
            for (int j = 0; j < EDIM; j++) ba += __ldg(b2 + j) * __ldg(Wp + (size_t)j * EDIM + tid);
            b2ps[tid] = ba;
        }
    }
    __syncthreads();

    {   // fourier scratch in A1 region
        float* scr = (float*)(smem + OFF_A1);
        for (int t = tid; t < 960; t += NTHR) {
            int d = t / 15, i = t - d * 15;
            float coordf = (float)d * (float)(3.14 / 64.0);
            float fr = coordf * (float)(1 << i);
            scr[d * 32 + i]      = (float)sin((double)fr);
            scr[d * 32 + 15 + i] = (float)cos((double)fr);
            if (i == 0) scr[d * 32 + 30] = coordf;
        }
    }
    __syncthreads();

    {   // table rows -> B2 steps 8..11
        const float* scr = (const float*)(smem + OFF_A1);
        int n = tid & 127, dh = tid >> 7;
        float wpc[31];
        #pragma unroll
        for (int c = 0; c < 31; c++) wpc[c] = __ldg(Wp + (size_t)(EDIM + c) * EDIM + n);
        float bb = b2ps[n];
        #pragma unroll 4
        for (int u = 0; u < 32; u++) {
            int d = dh + 2 * u;
            float acc = bb;
            #pragma unroll
            for (int c = 0; c < 31; c++) acc += scr[d * 32 + c] * wpc[c];
            B2h[b_half_idx(128 + d, n)] = __float2half(acc);
        }
    }
    __syncthreads();

    // zero A1 K-pad words (kp 36..39) for this warp's 32 rows
    uint32_t* A1w = A1u + mbase * A1_STRIDE;
    for (int i = lid; i < 128; i += 32)
        A1w[(i >> 2) * A1_STRIDE + 36 + (i & 3)] = 0;

    uint32_t* GdstA = A1w + erow * A1_STRIDE + (lid & 1) * 18;
    uint32_t* GdstB = A1w + (16 + erow) * A1_STRIDE + (lid & 1) * 18;

    // ldmatrix lane addresses (row = lid&15, k-chunk = lid>>4)
    const uint32_t a1_sa = smem_u32(A1w);
    const uint32_t a_base0 = a1_sa + (((lid & 15) * A1_STRIDE + (lid >> 4) * 4) << 2);
    const uint32_t a_base1 = a_base0 + 16 * A1_STRIDE * 4;

    // first tile: stage + extract both batches
    {
        int t0 = blockIdx.x;
        #pragma unroll
        for (int b = 0; b < 2; b++) {
            int pix0 = t0 * (TILE_M / 4) + wid * 8 + b * 4;
            stage_records(rec_sa, cost + (size_t)pix0 * (GGRP * DDISP) + lid * 4, lid);
            int row = 16 * b + erow;
            int draw = __ldg(label + t0 * TILE_M + mbase + row);
            if ((lid & 1) == 0) {
                labels_s[mbase + row] = draw;
                if (out_label) out_label[t0 * TILE_M + mbase + row] = (float)draw;
            }
            CP_WAIT0();
            __syncwarp();
            int dcl = draw < 0 ? 0 : (draw > 63 ? 63 : draw);
            GWin w = gwin(dcl);
            extract_windows(recw, prow, grp4, w, b ? GdstB : GdstA);
            __syncwarp();
        }
    }

    // ================= MAIN LOOP =================
    int cb = 0;
    for (int tile = blockIdx.x; tile < NTILES; tile += GRID_X) {
        const int m0 = tile * TILE_M;
        const int nxt = tile + GRID_X;
        const bool hn = nxt < NTILES;

        int drawA = 0, drawB = 0;
        if (hn) {
            drawA = __ldg(label + nxt * TILE_M + mbase + erow);
            drawB = __ldg(label + nxt * TILE_M + mbase + 16 + erow);
        }

        int dga[2], dgb[2];
        #pragma unroll
        for (int i = 0; i < 2; i++) {
            int d0 = labels_s[cb * TILE_M + mbase + 16 * i + g];
            int d1 = labels_s[cb * TILE_M + mbase + 16 * i + g + 8];
            dga[i] = d0 < 0 ? 0 : (d0 > 63 ? 63 : d0);
            dgb[i] = d1 < 0 ? 0 : (d1 > 63 ? 63 : d1);
        }

        // ---- GEMM1 (two n-halves): ldmatrix A + LDS.128 B -> ha[2][8][4] ----
        uint32_t ha[2][8][4];
        #pragma unroll
        for (int hf = 0; hf < 2; hf++) {
            float acc1[2][8][4];
            #pragma unroll
            for (int i = 0; i < 2; i++)
                #pragma unroll
                for (int j = 0; j < 8; j++)
                    #pragma unroll
                    for (int u = 0; u < 4; u++) acc1[i][j][u] = 0.f;
            #pragma unroll
            for (int s = 0; s < 5; s++) {
                uint32_t a[2][4];
                ldsm_x4(a[0], a_base0 + s * 32);
                ldsm_x4(a[1], a_base1 + s * 32);
                const uint4* bq = B1q + s * BQ_S + ti * 66 + (4 * hf) * 8 + g;
                #pragma unroll
                for (int jp = 0; jp < 4; jp++) {
                    uint4 b = bq[jp * 8];
                    mma_f16(acc1[0][2 * jp],     a[0][0], a[0][1], a[0][2], a[0][3], b.x, b.y);
                    mma_f16(acc1[1][2 * jp],     a[1][0], a[1][1], a[1][2], a[1][3], b.x, b.y);
                    mma_f16(acc1[0][2 * jp + 1], a[0][0], a[0][1], a[0][2], a[0][3], b.z, b.w);
                    mma_f16(acc1[1][2 * jp + 1], a[1][0], a[1][1], a[1][2], a[1][3], b.z, b.w);
                }
            }
            // gelu + repack into ha steps 4*hf .. 4*hf+3
            #pragma unroll
            for (int sl = 0; sl < 4; sl++) {
                int j0 = 2 * sl, j1 = 2 * sl + 1;
                float2 bb0 = *(const float2*)(b1s + 64 * hf + 8 * j0 + 2 * ti);
                float2 bb1 = *(const float2*)(b1s + 64 * hf + 8 * j1 + 2 * ti);
                #pragma unroll
                for (int i = 0; i < 2; i++) {
                    ha[i][4 * hf + sl][0] = pack_h2(gelu_fast(acc1[i][j0][0] + bb0.x),
                                                   gelu_fast(acc1[i][j0][1] + bb0.y));
                    ha[i][4 * hf + sl][1] = pack_h2(gelu_fast(acc1[i][j0][2] + bb0.x),
                                                   gelu_fast(acc1[i][j0][3] + bb0.y));
                    ha[i][4 * hf + sl][2] = pack_h2(gelu_fast(acc1[i][j1][0] + bb1.x),
                                                   gelu_fast(acc1[i][j1][1] + bb1.y));
                    ha[i][4 * hf + sl][3] = pack_h2(gelu_fast(acc1[i][j1][2] + bb1.x),
                                                   gelu_fast(acc1[i][j1][3] + bb1.y));
                }
            }
        }
        __syncwarp();   // A1 fully consumed

        // ---- stage batch A of next tile (covered by GEMM2 half 0) ----
        if (hn) {
            int pix0 = nxt * (TILE_M / 4) + wid * 8;
            stage_records(rec_sa, cost + (size_t)pix0 * (GGRP * DDISP) + lid * 4, lid);
        }

        // ---- GEMM2 + epilogue, two n-halves; LDS.128 B shared across m-blocks ----
        #pragma unroll
        for (int hf = 0; hf < 2; hf++) {
            float acc2[2][8][4];
            #pragma unroll
            for (int i = 0; i < 2; i++)
                #pragma unroll
                for (int j = 0; j < 8; j++)
                    #pragma unroll
                    for (int u = 0; u < 4; u++) acc2[i][j][u] = 0.f;
            #pragma unroll
            for (int s = 0; s < 8; s++) {
                const uint4* bq = B2q + s * BQ_S + ti * 66 + (4 * hf) * 8 + g;
                #pragma unroll
                for (int jp = 0; jp < 4; jp++) {
                    uint4 b = bq[jp * 8];
                    mma_f16(acc2[0][2 * jp],     ha[0][s][0], ha[0][s][1], ha[0][s][2], ha[0][s][3], b.x, b.y);
                    mma_f16(acc2[1][2 * jp],     ha[1][s][0], ha[1][s][1], ha[1][s][2], ha[1][s][3], b.x, b.y);
                    mma_f16(acc2[0][2 * jp + 1], ha[0][s][0], ha[0][s][1], ha[0][s][2], ha[0][s][3], b.z, b.w);
                    mma_f16(acc2[1][2 * jp + 1], ha[1][s][0], ha[1][s][1], ha[1][s][2], ha[1][s][3], b.z, b.w);
                }
            }
            #pragma unroll
            for (int s = 0; s < 4; s++) {
                int kb = 16 * s + 2 * ti;
                const uint4* bq = B2q + (8 + s) * BQ_S + ti * 66 + (4 * hf) * 8 + g;
                #pragma unroll
                for (int i = 0; i < 2; i++) {
                    uint32_t a0 = oh2(dga[i], kb);
                    uint32_t a1 = oh2(dgb[i], kb);
                    uint32_t a2 = oh2(dga[i], kb + 8);
                    uint32_t a3 = oh2(dgb[i], kb + 8);
                    #pragma unroll
                    for (int jp = 0; jp < 4; jp++) {
                        uint4 b = bq[jp * 8];
                        mma_f16(acc2[i][2 * jp],     a0, a1, a2, a3, b.x, b.y);
                        mma_f16(acc2[i][2 * jp + 1], a0, a1, a2, a3, b.z, b.w);
                    }
                }
            }
            // epilogue for this half: streaming stores (write-once output)
            #pragma unroll
            for (int i = 0; i < 2; i++) {
                float* o0 = out_embed + (size_t)(m0 + mbase + 16 * i + g) * EDIM + 64 * hf + 2 * ti;
                float* o1 = out_embed + (size_t)(m0 + mbase + 16 * i + g + 8) * EDIM + 64 * hf + 2 * ti;
                #pragma unroll
                for (int j = 0; j < 8; j++) {
                    __stcs((float2*)(o0 + 8 * j), make_float2(acc2[i][j][0], acc2[i][j][1]));
                    __stcs((float2*)(o1 + 8 * j), make_float2(acc2[i][j][2], acc2[i][j][3]));
                }
            }

            // between halves: land batch A, extract, stage batch B
            if (hf == 0 && hn) {
                CP_WAIT0();
                __syncwarp();
                int dcl = drawA < 0 ? 0 : (drawA > 63 ? 63 : drawA);
                GWin w = gwin(dcl);
                extract_windows(recw, prow, grp4, w, GdstA);
                if ((lid & 1) == 0) {
                    labels_s[(cb ^ 1) * TILE_M + mbase + erow] = drawA;
                    if (out_label) out_label[nxt * TILE_M + mbase + erow] = (float)drawA;
                }
                __syncwarp();
                int pix0 = nxt * (TILE_M / 4) + wid * 8 + 4;
                stage_records(rec_sa, cost + (size_t)pix0 * (GGRP * DDISP) + lid * 4, lid);
            }
        }

        // ---- land batch B, extract ----
        if (hn) {
            CP_WAIT0();
            __syncwarp();
            int dcl = drawB < 0 ? 0 : (drawB > 63 ? 63 : drawB);
            GWin w = gwin(dcl);
            extract_windows(recw, prow, grp4, w, GdstB);
            if ((lid & 1) == 0) {
                labels_s[(cb ^ 1) * TILE_M + mbase + 16 + erow] = drawB;
                if (out_label) out_label[nxt * TILE_M + mbase + 16 + erow] = (float)drawB;
            }
        }
        __syncwarp();
        cb ^= 1;
    }
}

// ---------------- launch ----------------
extern "C" void kernel_launch(void* const* d_in, const int* in_sizes, int n_in,
                              void* d_out, int out_size) {
    const float* cost  = (const float*)d_in[0];
    const int*   label = (const int*)d_in[1];
    // d_in[2] = context (unused: layers=[] passthrough)
    const float* W1 = (const float*)d_in[3];
    const float* b1 = (const float*)d_in[4];
    const float* W2 = (const float*)d_in[5];
    const float* b2 = (const float*)d_in[6];
    const float* Wp = (const float*)d_in[7];

    float* out = (float*)d_out;
    float* out_label = (out_size >= TOT_ELEMS) ? (out + EMB_ELEMS) : nullptr;

    cudaFuncSetAttribute(propagation_kernel,
                         cudaFuncAttributeMaxDynamicSharedMemorySize, SMEM_TOTAL);

    propagation_kernel<<<GRID_X, NTHR, SMEM_TOTAL>>>(cost, label, W1, b1, W2, b2, Wp,
                                                     out, out_label);
}